// round 4
// baseline (speedup 1.0000x reference)
#include <cuda_runtime.h>
#include <cstdint>

#define N_ROWS  16384   // B*E = 32*512
#define C_DIM   64
#define O_CODES 8192
#define MTILE   64      // rows per block
#define KTILE   128     // codes per smem tile

// Scratch (no device allocation allowed -> __device__ globals)
__device__ float  g_xx[N_ROWS];
__device__ float  g_ww[O_CODES];
__device__ int    g_inds[N_ROWS];
__device__ double g_acc[3];

// ---------------------------------------------------------------------------
// Kernel A: row norms ||x||^2, code norms ||w||^2, zero loss accumulators
// ---------------------------------------------------------------------------
__global__ void prep_kernel(const float* __restrict__ latents,
                            const float* __restrict__ codebook) {
    int t = blockIdx.x * blockDim.x + threadIdx.x;
    if (t == 0) { g_acc[0] = 0.0; g_acc[1] = 0.0; g_acc[2] = 0.0; }
    if (t < N_ROWS) {
        const float4* p = reinterpret_cast<const float4*>(latents + (size_t)t * C_DIM);
        float s = 0.f;
        #pragma unroll
        for (int q = 0; q < 16; q++) {
            float4 v = p[q];
            s = fmaf(v.x, v.x, s); s = fmaf(v.y, v.y, s);
            s = fmaf(v.z, v.z, s); s = fmaf(v.w, v.w, s);
        }
        g_xx[t] = s;
    } else if (t < N_ROWS + O_CODES) {
        int k = t - N_ROWS;
        const float4* p = reinterpret_cast<const float4*>(codebook + (size_t)k * C_DIM);
        float s = 0.f;
        #pragma unroll
        for (int q = 0; q < 16; q++) {
            float4 v = p[q];
            s = fmaf(v.x, v.x, s); s = fmaf(v.y, v.y, s);
            s = fmaf(v.z, v.z, s); s = fmaf(v.w, v.w, s);
        }
        g_ww[k] = s;
    }
}

// ---------------------------------------------------------------------------
// Packed fp32x2 FMA (per-lane IEEE RN, identical rounding to scalar FFMA).
// ptxas will not auto-generate FFMA2 from C++; must come from PTX.
// ---------------------------------------------------------------------------
__device__ __forceinline__ void fma2(unsigned long long& d,
                                     unsigned long long a,
                                     unsigned long long b) {
    asm("fma.rn.f32x2 %0, %1, %2, %0;" : "+l"(d) : "l"(a), "l"(b));
}

// ---------------------------------------------------------------------------
// Kernel B: distance GEMM + per-row argmin (first-index tie-break).
//   dist = fl( fl(xx + ww_k) - fl(2 * dot(x, w_k)) )  -- exact op chain of ref
//   block: 256 thr = 8 warps; warp w owns rows [base + 8w, base + 8w + 8)
//   lane owns 4 codes per K-tile: {4*lane .. 4*lane+3} (as two f32x2 pairs)
//   smem: wsm[j][KTILE] plain fp32 (transposed codes), xd[j][MTILE] as (x,x) pairs
// ---------------------------------------------------------------------------
__global__ void __launch_bounds__(256, 2)
argmin_kernel(const float* __restrict__ latents,
              const float* __restrict__ codebook) {
    extern __shared__ unsigned char smem_raw[];
    float* wsm = reinterpret_cast<float*>(smem_raw);                                   // 64*KTILE*4 = 32KB
    unsigned long long* xd =
        reinterpret_cast<unsigned long long*>(smem_raw + 64 * KTILE * 4);              // 64*MTILE*8 = 32KB

    const int tid  = threadIdx.x;
    const int lane = tid & 31;
    const int wid  = tid >> 5;
    const int rowBase = blockIdx.x * MTILE;

    // Stage x tile, duplicated into both f32x2 halves: xd[j][r] = (x_r[j], x_r[j])
    for (int idx = tid; idx < 64 * MTILE; idx += 256) {
        int r = idx & (MTILE - 1);
        int j = idx >> 6;
        unsigned long long u =
            (unsigned long long)__float_as_uint(latents[(size_t)(rowBase + r) * C_DIM + j]);
        xd[j * MTILE + r] = u | (u << 32);
    }

    float xxr[8];
    #pragma unroll
    for (int rr = 0; rr < 8; rr++) xxr[rr] = g_xx[rowBase + wid * 8 + rr];

    float bestD[8]; int bestI[8];
    #pragma unroll
    for (int rr = 0; rr < 8; rr++) { bestD[rr] = 3.402823466e38f; bestI[rr] = 0; }

    for (int kt = 0; kt < O_CODES; kt += KTILE) {
        __syncthreads();   // protect wsm reuse (also covers initial xd fill)

        // Stage codebook tile transposed: wsm[j][k_local]. Two threads per code.
        {
            int cl = tid >> 1;
            int j0 = (tid & 1) * 32;
            const float4* src =
                reinterpret_cast<const float4*>(codebook + (size_t)(kt + cl) * C_DIM + j0);
            #pragma unroll
            for (int q = 0; q < 8; q++) {
                float4 v = src[q];
                int j = j0 + q * 4;
                wsm[(j + 0) * KTILE + cl] = v.x;
                wsm[(j + 1) * KTILE + cl] = v.y;
                wsm[(j + 2) * KTILE + cl] = v.z;
                wsm[(j + 3) * KTILE + cl] = v.w;
            }
        }
        float wwv[4];
        #pragma unroll
        for (int q = 0; q < 4; q++) wwv[q] = g_ww[kt + 4 * lane + q];
        __syncthreads();

        // acc[row][pair]: pair0 = codes (4l, 4l+1), pair1 = (4l+2, 4l+3)
        unsigned long long acc[8][2];
        #pragma unroll
        for (int rr = 0; rr < 8; rr++) { acc[rr][0] = 0ull; acc[rr][1] = 0ull; }

        #pragma unroll 8
        for (int j = 0; j < 64; j++) {
            // 4 codes of this lane for element j: one conflict-free LDS.128
            ulonglong2 wv = *reinterpret_cast<const ulonglong2*>(wsm + j * KTILE + lane * 4);
            // 8 duplicated x values (rows of this warp): broadcast LDS.128 x4
            const ulonglong2* xr =
                reinterpret_cast<const ulonglong2*>(xd + j * MTILE + wid * 8);
            ulonglong2 x01 = xr[0], x23 = xr[1], x45 = xr[2], x67 = xr[3];
            fma2(acc[0][0], wv.x, x01.x); fma2(acc[0][1], wv.y, x01.x);
            fma2(acc[1][0], wv.x, x01.y); fma2(acc[1][1], wv.y, x01.y);
            fma2(acc[2][0], wv.x, x23.x); fma2(acc[2][1], wv.y, x23.x);
            fma2(acc[3][0], wv.x, x23.y); fma2(acc[3][1], wv.y, x23.y);
            fma2(acc[4][0], wv.x, x45.x); fma2(acc[4][1], wv.y, x45.x);
            fma2(acc[5][0], wv.x, x45.y); fma2(acc[5][1], wv.y, x45.y);
            fma2(acc[6][0], wv.x, x67.x); fma2(acc[6][1], wv.y, x67.x);
            fma2(acc[7][0], wv.x, x67.y); fma2(acc[7][1], wv.y, x67.y);
        }

        // dist + running min. Codes visited in ascending k per thread, so a
        // strict '<' preserves the reference's first-index tie-break.
        #pragma unroll
        for (int rr = 0; rr < 8; rr++) {
            #pragma unroll
            for (int p = 0; p < 2; p++) {
                unsigned long long a = acc[rr][p];
                float dlo = __uint_as_float((unsigned)(a & 0xffffffffull));
                float dhi = __uint_as_float((unsigned)(a >> 32));
                int k0 = kt + 4 * lane + 2 * p;
                float d = __fsub_rn(__fadd_rn(xxr[rr], wwv[2 * p]),
                                    __fmul_rn(2.0f, dlo));
                if (d < bestD[rr]) { bestD[rr] = d; bestI[rr] = k0; }
                d = __fsub_rn(__fadd_rn(xxr[rr], wwv[2 * p + 1]),
                              __fmul_rn(2.0f, dhi));
                if (d < bestD[rr]) { bestD[rr] = d; bestI[rr] = k0 + 1; }
            }
        }
    }

    // Warp-level argmin reduction per row (rows are exclusive per warp).
    #pragma unroll
    for (int rr = 0; rr < 8; rr++) {
        float d = bestD[rr]; int i = bestI[rr];
        #pragma unroll
        for (int o = 16; o > 0; o >>= 1) {
            float od = __shfl_down_sync(0xffffffffu, d, o);
            int   oi = __shfl_down_sync(0xffffffffu, i, o);
            if (od < d || (od == d && oi < i)) { d = od; i = oi; }
        }
        if (lane == 0) g_inds[rowBase + wid * 8 + rr] = i;
    }
}

// ---------------------------------------------------------------------------
// Kernel C: gather codes, write out = fl(latents + fl(q_noisy - latents)),
// accumulate the three MSE sums in double.
// ---------------------------------------------------------------------------
__global__ void epilogue_kernel(const float* __restrict__ latents,
                                const float* __restrict__ y,
                                const float* __restrict__ codebook,
                                const float* __restrict__ noise,
                                float* __restrict__ out, int nElems) {
    double s0 = 0.0, s1 = 0.0, s2 = 0.0;
    int stride = gridDim.x * blockDim.x;
    for (int e = blockIdx.x * blockDim.x + threadIdx.x; e < nElems; e += stride) {
        int i = e >> 6, c = e & 63;
        float lat = latents[e];
        float yv  = y[e];
        int kd = g_inds[i];
        // jnp.round = round-half-to-even = rintf
        int off = (int)rintf(__fmul_rn(noise[i], 0.5f));
        int kn = kd + off;
        kn = kn < 0 ? 0 : (kn > O_CODES - 1 ? O_CODES - 1 : kn);
        float qd = codebook[(kd << 6) + c];
        float qn = codebook[(kn << 6) + c];
        float diff = __fsub_rn(qn, lat);           // q_noisy - latents (codebook loss term)
        float ov   = __fadd_rn(lat, diff);         // straight-through output (exact ref ops)
        out[e] = ov;
        float r  = __fsub_rn(ov, yv);              // recon term
        float cm = __fsub_rn(lat, qd);             // commit term
        s0 += (double)r  * (double)r;
        s1 += (double)cm * (double)cm;
        s2 += (double)diff * (double)diff;
    }
    #pragma unroll
    for (int o = 16; o > 0; o >>= 1) {
        s0 += __shfl_down_sync(0xffffffffu, s0, o);
        s1 += __shfl_down_sync(0xffffffffu, s1, o);
        s2 += __shfl_down_sync(0xffffffffu, s2, o);
    }
    if ((threadIdx.x & 31) == 0) {
        atomicAdd(&g_acc[0], s0);
        atomicAdd(&g_acc[1], s1);
        atomicAdd(&g_acc[2], s2);
    }
}

// ---------------------------------------------------------------------------
// Kernel D: finalize loss scalar
// ---------------------------------------------------------------------------
__global__ void finish_kernel(float* __restrict__ out, int lossStart, int lossEnd) {
    double n = (double)(N_ROWS) * (double)C_DIM;
    float loss = (float)(g_acc[0] / n + 0.25 * (g_acc[1] / n) + g_acc[2] / n);
    for (int i = lossStart + (int)threadIdx.x; i < lossEnd; i += blockDim.x) out[i] = loss;
}

// ---------------------------------------------------------------------------
extern "C" void kernel_launch(void* const* d_in, const int* in_sizes, int n_in,
                              void* d_out, int out_size) {
    const float* latents  = (const float*)d_in[0];  // [32,512,64]
    const float* y        = (const float*)d_in[1];  // [32,512,64]
    const float* codebook = (const float*)d_in[2];  // [8192,64]
    const float* noise    = (const float*)d_in[3];  // [16384]
    float* out = (float*)d_out;
    int nElems = in_sizes[0];                        // 1048576

    cudaFuncSetAttribute(argmin_kernel,
                         cudaFuncAttributeMaxDynamicSharedMemorySize, 65536);

    prep_kernel<<<(N_ROWS + O_CODES + 255) / 256, 256>>>(latents, codebook);
    argmin_kernel<<<N_ROWS / MTILE, 256, 65536>>>(latents, codebook);
    epilogue_kernel<<<1024, 256>>>(latents, y, codebook, noise, out, nElems);
    if (out_size > nElems) finish_kernel<<<1, 32>>>(out, nElems, out_size);
}

// round 5
// speedup vs baseline: 1.1004x; 1.1004x over previous
#include <cuda_runtime.h>
#include <cstdint>

#define N_ROWS  16384   // B*E = 32*512
#define C_DIM   64
#define O_CODES 8192
#define MTILE   64      // rows per block
#define KTILE   128     // codes per smem tile
#define KSPLIT  8
#define K_PER_BLOCK (O_CODES / KSPLIT)   // 1024
#define NTILES  (K_PER_BLOCK / KTILE)    // 8

// Scratch (no device allocation allowed -> __device__ globals)
__device__ float              g_xx[N_ROWS];
__device__ float              g_ww[O_CODES];
__device__ unsigned long long g_best[N_ROWS];   // (dist_bits<<32)|index, min = best
__device__ double             g_acc[3];

// ---------------------------------------------------------------------------
// Kernel A: row norms ||x||^2, code norms ||w||^2, init best keys + loss accs
// ---------------------------------------------------------------------------
__global__ void prep_kernel(const float* __restrict__ latents,
                            const float* __restrict__ codebook) {
    int t = blockIdx.x * blockDim.x + threadIdx.x;
    if (t == 0) { g_acc[0] = 0.0; g_acc[1] = 0.0; g_acc[2] = 0.0; }
    if (t < N_ROWS) {
        const float4* p = reinterpret_cast<const float4*>(latents + (size_t)t * C_DIM);
        float s = 0.f;
        #pragma unroll
        for (int q = 0; q < 16; q++) {
            float4 v = p[q];
            s = fmaf(v.x, v.x, s); s = fmaf(v.y, v.y, s);
            s = fmaf(v.z, v.z, s); s = fmaf(v.w, v.w, s);
        }
        g_xx[t] = s;
        g_best[t] = 0xffffffffffffffffull;
    } else if (t < N_ROWS + O_CODES) {
        int k = t - N_ROWS;
        const float4* p = reinterpret_cast<const float4*>(codebook + (size_t)k * C_DIM);
        float s = 0.f;
        #pragma unroll
        for (int q = 0; q < 16; q++) {
            float4 v = p[q];
            s = fmaf(v.x, v.x, s); s = fmaf(v.y, v.y, s);
            s = fmaf(v.z, v.z, s); s = fmaf(v.w, v.w, s);
        }
        g_ww[k] = s;
    }
}

// ---------------------------------------------------------------------------
// Packed fp32x2 FMA (per-lane IEEE RN, identical rounding to scalar FFMA).
// ptxas will not auto-generate FFMA2 from C++; must come from PTX.
// ---------------------------------------------------------------------------
__device__ __forceinline__ void fma2(unsigned long long& d,
                                     unsigned long long a,
                                     unsigned long long b) {
    asm("fma.rn.f32x2 %0, %1, %2, %0;" : "+l"(d) : "l"(a), "l"(b));
}

#define FMA_BLOCK(W, X01, X23, X45, X67)                              \
    fma2(acc[0][0], (W).x, (X01).x); fma2(acc[0][1], (W).y, (X01).x); \
    fma2(acc[1][0], (W).x, (X01).y); fma2(acc[1][1], (W).y, (X01).y); \
    fma2(acc[2][0], (W).x, (X23).x); fma2(acc[2][1], (W).y, (X23).x); \
    fma2(acc[3][0], (W).x, (X23).y); fma2(acc[3][1], (W).y, (X23).y); \
    fma2(acc[4][0], (W).x, (X45).x); fma2(acc[4][1], (W).y, (X45).x); \
    fma2(acc[5][0], (W).x, (X45).y); fma2(acc[5][1], (W).y, (X45).y); \
    fma2(acc[6][0], (W).x, (X67).x); fma2(acc[6][1], (W).y, (X67).x); \
    fma2(acc[7][0], (W).x, (X67).y); fma2(acc[7][1], (W).y, (X67).y)

// ---------------------------------------------------------------------------
// Kernel B: distance GEMM + per-row argmin, K-split across blockIdx.y.
//   dist = fl( fl(xx + ww_k) - fl(2 * dot(x, w_k)) )  -- exact op chain of ref
//   block: 256 thr = 8 warps; warp w owns rows [base + 8w, base + 8w + 8)
//   lane owns 4 codes per K-tile as two f32x2 pairs.
//   Cross-block combine: atomicMin on key = (dist_bits<<32)|k. Positive-float
//   bit order is monotone, so min-key == (min dist, then min index) — exactly
//   the reference's first-index tie-break, globally.
// ---------------------------------------------------------------------------
__global__ void __launch_bounds__(256, 2)
argmin_kernel(const float* __restrict__ latents,
              const float* __restrict__ codebook) {
    extern __shared__ unsigned char smem_raw[];
    float* wsm = reinterpret_cast<float*>(smem_raw);                        // 64*KTILE*4 = 32KB
    unsigned long long* xd =
        reinterpret_cast<unsigned long long*>(smem_raw + 64 * KTILE * 4);   // 64*MTILE*8 = 32KB

    const int tid  = threadIdx.x;
    const int lane = tid & 31;
    const int wid  = tid >> 5;
    const int rowBase = blockIdx.x * MTILE;
    const int kBase   = blockIdx.y * K_PER_BLOCK;

    // Stage x tile, duplicated into both f32x2 halves: xd[j][r] = (x_r[j], x_r[j])
    for (int idx = tid; idx < 64 * MTILE; idx += 256) {
        int r = idx & (MTILE - 1);
        int j = idx >> 6;
        unsigned long long u =
            (unsigned long long)__float_as_uint(latents[(size_t)(rowBase + r) * C_DIM + j]);
        xd[j * MTILE + r] = u | (u << 32);
    }

    float xxr[8];
    #pragma unroll
    for (int rr = 0; rr < 8; rr++) xxr[rr] = g_xx[rowBase + wid * 8 + rr];

    float bestD[8]; int bestI[8];
    #pragma unroll
    for (int rr = 0; rr < 8; rr++) { bestD[rr] = 3.402823466e38f; bestI[rr] = 0; }

    const float* wbase = wsm + lane * 4;
    const unsigned long long* xbase = xd + wid * 8;

    for (int t = 0; t < NTILES; t++) {
        const int kt = kBase + t * KTILE;
        __syncthreads();   // wsm reuse barrier (also covers initial xd fill)

        // Stage codebook tile transposed: wsm[j][k_local]. Two threads per code.
        {
            int cl = tid >> 1;
            int j0 = (tid & 1) * 32;
            const float4* src =
                reinterpret_cast<const float4*>(codebook + (size_t)(kt + cl) * C_DIM + j0);
            #pragma unroll
            for (int q = 0; q < 8; q++) {
                float4 v = src[q];
                int j = j0 + q * 4;
                wsm[(j + 0) * KTILE + cl] = v.x;
                wsm[(j + 1) * KTILE + cl] = v.y;
                wsm[(j + 2) * KTILE + cl] = v.z;
                wsm[(j + 3) * KTILE + cl] = v.w;
            }
        }
        __syncthreads();

        unsigned long long acc[8][2];
        #pragma unroll
        for (int rr = 0; rr < 8; rr++) { acc[rr][0] = 0ull; acc[rr][1] = 0ull; }

        // Depth-1 software-pipelined, ping-pong operand buffers, rolled loop:
        // keeps live regs ~110 (no spills) while the fma pipe stays the binder.
        #define LDW(j)   (*reinterpret_cast<const ulonglong2*>(wbase + (j) * KTILE))
        #define LDX(j,q) (reinterpret_cast<const ulonglong2*>(xbase + (j) * MTILE))[q]

        ulonglong2 wA  = LDW(0);
        ulonglong2 xA0 = LDX(0, 0), xA1 = LDX(0, 1), xA2 = LDX(0, 2), xA3 = LDX(0, 3);
        #pragma unroll 1
        for (int jj = 0; jj < 32; jj++) {
            const int j1 = 2 * jj + 1;
            ulonglong2 wB  = LDW(j1);
            ulonglong2 xB0 = LDX(j1, 0), xB1 = LDX(j1, 1),
                       xB2 = LDX(j1, 2), xB3 = LDX(j1, 3);
            FMA_BLOCK(wA, xA0, xA1, xA2, xA3);
            if (jj < 31) {
                const int j2 = 2 * jj + 2;
                wA  = LDW(j2);
                xA0 = LDX(j2, 0); xA1 = LDX(j2, 1);
                xA2 = LDX(j2, 2); xA3 = LDX(j2, 3);
            }
            FMA_BLOCK(wB, xB0, xB1, xB2, xB3);
        }
        #undef LDW
        #undef LDX

        // dist + running min. Codes visited in ascending k per thread, so a
        // strict '<' preserves the reference's first-index tie-break.
        const float4 ww4 = *reinterpret_cast<const float4*>(g_ww + kt + 4 * lane);
        const float wwv[4] = { ww4.x, ww4.y, ww4.z, ww4.w };
        #pragma unroll
        for (int rr = 0; rr < 8; rr++) {
            #pragma unroll
            for (int p = 0; p < 2; p++) {
                unsigned long long a = acc[rr][p];
                float dlo = __uint_as_float((unsigned)(a & 0xffffffffull));
                float dhi = __uint_as_float((unsigned)(a >> 32));
                int k0 = kt + 4 * lane + 2 * p;
                float d = __fsub_rn(__fadd_rn(xxr[rr], wwv[2 * p]),
                                    __fmul_rn(2.0f, dlo));
                if (d < bestD[rr]) { bestD[rr] = d; bestI[rr] = k0; }
                d = __fsub_rn(__fadd_rn(xxr[rr], wwv[2 * p + 1]),
                              __fmul_rn(2.0f, dhi));
                if (d < bestD[rr]) { bestD[rr] = d; bestI[rr] = k0 + 1; }
            }
        }
    }

    // Warp argmin per row (rows exclusive per warp), then global combine.
    #pragma unroll
    for (int rr = 0; rr < 8; rr++) {
        unsigned long long key =
            ((unsigned long long)__float_as_uint(bestD[rr]) << 32) |
            (unsigned)bestI[rr];
        #pragma unroll
        for (int o = 16; o > 0; o >>= 1) {
            unsigned long long ok = __shfl_down_sync(0xffffffffu, key, o);
            if (ok < key) key = ok;
        }
        if (lane == 0) atomicMin(&g_best[rowBase + wid * 8 + rr], key);
    }
}

// ---------------------------------------------------------------------------
// Kernel C: gather codes, write out = fl(latents + fl(q_noisy - latents)),
// accumulate the three MSE sums in double.
// ---------------------------------------------------------------------------
__global__ void epilogue_kernel(const float* __restrict__ latents,
                                const float* __restrict__ y,
                                const float* __restrict__ codebook,
                                const float* __restrict__ noise,
                                float* __restrict__ out, int nElems) {
    double s0 = 0.0, s1 = 0.0, s2 = 0.0;
    int stride = gridDim.x * blockDim.x;
    for (int e = blockIdx.x * blockDim.x + threadIdx.x; e < nElems; e += stride) {
        int i = e >> 6, c = e & 63;
        float lat = latents[e];
        float yv  = y[e];
        int kd = (int)(g_best[i] & 0xffffffffull);
        // jnp.round = round-half-to-even = rintf
        int off = (int)rintf(__fmul_rn(noise[i], 0.5f));
        int kn = kd + off;
        kn = kn < 0 ? 0 : (kn > O_CODES - 1 ? O_CODES - 1 : kn);
        float qd = codebook[(kd << 6) + c];
        float qn = codebook[(kn << 6) + c];
        float diff = __fsub_rn(qn, lat);           // q_noisy - latents (codebook loss term)
        float ov   = __fadd_rn(lat, diff);         // straight-through output (exact ref ops)
        out[e] = ov;
        float r  = __fsub_rn(ov, yv);              // recon term
        float cm = __fsub_rn(lat, qd);             // commit term
        s0 += (double)r  * (double)r;
        s1 += (double)cm * (double)cm;
        s2 += (double)diff * (double)diff;
    }
    #pragma unroll
    for (int o = 16; o > 0; o >>= 1) {
        s0 += __shfl_down_sync(0xffffffffu, s0, o);
        s1 += __shfl_down_sync(0xffffffffu, s1, o);
        s2 += __shfl_down_sync(0xffffffffu, s2, o);
    }
    if ((threadIdx.x & 31) == 0) {
        atomicAdd(&g_acc[0], s0);
        atomicAdd(&g_acc[1], s1);
        atomicAdd(&g_acc[2], s2);
    }
}

// ---------------------------------------------------------------------------
// Kernel D: finalize loss scalar
// ---------------------------------------------------------------------------
__global__ void finish_kernel(float* __restrict__ out, int lossStart, int lossEnd) {
    double n = (double)(N_ROWS) * (double)C_DIM;
    float loss = (float)(g_acc[0] / n + 0.25 * (g_acc[1] / n) + g_acc[2] / n);
    for (int i = lossStart + (int)threadIdx.x; i < lossEnd; i += blockDim.x) out[i] = loss;
}

// ---------------------------------------------------------------------------
extern "C" void kernel_launch(void* const* d_in, const int* in_sizes, int n_in,
                              void* d_out, int out_size) {
    const float* latents  = (const float*)d_in[0];  // [32,512,64]
    const float* y        = (const float*)d_in[1];  // [32,512,64]
    const float* codebook = (const float*)d_in[2];  // [8192,64]
    const float* noise    = (const float*)d_in[3];  // [16384]
    float* out = (float*)d_out;
    int nElems = in_sizes[0];                        // 1048576

    cudaFuncSetAttribute(argmin_kernel,
                         cudaFuncAttributeMaxDynamicSharedMemorySize, 65536);

    prep_kernel<<<(N_ROWS + O_CODES + 255) / 256, 256>>>(latents, codebook);
    dim3 agrid(N_ROWS / MTILE, KSPLIT);
    argmin_kernel<<<agrid, 256, 65536>>>(latents, codebook);
    epilogue_kernel<<<1024, 256>>>(latents, y, codebook, noise, out, nElems);
    if (out_size > nElems) finish_kernel<<<1, 32>>>(out, nElems, out_size);
}